// round 1
// baseline (speedup 1.0000x reference)
#include <cuda_runtime.h>
#include <math.h>

#define TT 1024
#define BB 32
#define II 512
#define HH 512
#define NG 2048   // 4*H

// Scratch (allocation-free rule: __device__ globals)
__device__ float g_gates[(size_t)TT * BB * NG];   // 268 MB: x-projection for all timesteps
__device__ float g_hbuf[2][BB * HH];              // h double buffer
__device__ unsigned int g_bar_count;
__device__ unsigned int g_bar_gen;

// ---------------------------------------------------------------------------
// init: copy h0 into buffer 0, reset barrier state (graph-replay safe)
// ---------------------------------------------------------------------------
__global__ void init_kernel(const float* __restrict__ h0) {
    int t = blockIdx.x * blockDim.x + threadIdx.x;
    if (t < BB * HH) g_hbuf[0][t] = h0[t];
    if (t == 0) { g_bar_count = 0u; g_bar_gen = 0u; }
}

// ---------------------------------------------------------------------------
// gates_x[L=32768][2048] = X[L][512] @ W_ih[2048][512]^T + (b_ih + b_hh)
// 128x64 block tile, K-tile 32, 256 threads, 8x4 microtile.
// ---------------------------------------------------------------------------
__global__ __launch_bounds__(256) void gemm_x_kernel(
    const float* __restrict__ X, const float* __restrict__ W,
    const float* __restrict__ bih, const float* __restrict__ bhh)
{
    __shared__ float As[32][132];   // [k][m], padded stride 132 (16B-aligned, conflict-free)
    __shared__ float Bs[32][68];    // [k][n]
    const int tid = threadIdx.x;
    const int tx = tid & 15, ty = tid >> 4;
    const int m0 = blockIdx.x * 128, n0 = blockIdx.y * 64;

    float acc[8][4];
#pragma unroll
    for (int i = 0; i < 8; i++)
#pragma unroll
        for (int j = 0; j < 4; j++) acc[i][j] = 0.f;

    for (int k0 = 0; k0 < II; k0 += 32) {
#pragma unroll
        for (int i = 0; i < 4; i++) {           // A tile: 128x32 = 1024 float4
            int q = tid + i * 256;
            int r = q >> 3, c4 = (q & 7) * 4;
            float4 v = *(const float4*)&X[(size_t)(m0 + r) * II + k0 + c4];
            As[c4 + 0][r] = v.x; As[c4 + 1][r] = v.y;
            As[c4 + 2][r] = v.z; As[c4 + 3][r] = v.w;
        }
#pragma unroll
        for (int i = 0; i < 2; i++) {           // W tile: 64x32 = 512 float4
            int q = tid + i * 256;
            int r = q >> 3, c4 = (q & 7) * 4;
            float4 v = *(const float4*)&W[(size_t)(n0 + r) * II + k0 + c4];
            Bs[c4 + 0][r] = v.x; Bs[c4 + 1][r] = v.y;
            Bs[c4 + 2][r] = v.z; Bs[c4 + 3][r] = v.w;
        }
        __syncthreads();
#pragma unroll
        for (int k = 0; k < 32; k++) {
            float a[8], bf[4];
            *(float4*)&a[0] = *(const float4*)&As[k][ty * 8];
            *(float4*)&a[4] = *(const float4*)&As[k][ty * 8 + 4];
            *(float4*)&bf[0] = *(const float4*)&Bs[k][tx * 4];
#pragma unroll
            for (int i = 0; i < 8; i++)
#pragma unroll
                for (int j = 0; j < 4; j++)
                    acc[i][j] = fmaf(a[i], bf[j], acc[i][j]);
        }
        __syncthreads();
    }

    const int gn = n0 + tx * 4;
    const float b0 = bih[gn + 0] + bhh[gn + 0];
    const float b1 = bih[gn + 1] + bhh[gn + 1];
    const float b2 = bih[gn + 2] + bhh[gn + 2];
    const float b3 = bih[gn + 3] + bhh[gn + 3];
#pragma unroll
    for (int i = 0; i < 8; i++) {
        float4 v = make_float4(acc[i][0] + b0, acc[i][1] + b1,
                               acc[i][2] + b2, acc[i][3] + b3);
        *(float4*)&g_gates[(size_t)(m0 + ty * 8 + i) * NG + gn] = v;
    }
}

// ---------------------------------------------------------------------------
// Persistent recurrence: 128 CTAs x 128 threads, software grid barrier/step.
// CTA bid owns hidden units [bid*4, bid*4+4): 16 W_hh rows resident in SMEM.
// Thread (r = tid&15, bg = tid>>4): row r, batches bg*4..bg*4+3.
// c state lives in registers of the "pair" mapping (b = tid&31, hh = tid>>5).
// ---------------------------------------------------------------------------
__global__ __launch_bounds__(128) void lstm_rec_kernel(
    const float* __restrict__ Whh, const float* __restrict__ c0,
    float* __restrict__ out)
{
    __shared__ float sw[16 * 516];   // 16 rows x 512 (stride 516: aligned, conflict-free)
    __shared__ float sg[16 * 33];    // gate exchange [row][batch]

    const int tid  = threadIdx.x;
    const int r    = tid & 15;       // gate row within block (j = gate*4 + hh)
    const int bg   = tid >> 4;       // batch group 0..7
    const int hid0 = blockIdx.x * 4;

    // Stage this block's 16 W_hh rows into SMEM (once).
    for (int q = tid; q < 16 * 128; q += 128) {
        int j = q >> 7; int c4 = (q & 127) * 4;
        int g = j >> 2, hh = j & 3;
        float4 v = *(const float4*)&Whh[(size_t)(g * HH + hid0 + hh) * HH + c4];
        *(float4*)&sw[j * 516 + c4] = v;
    }

    const int b_p = tid & 31, hh_p = tid >> 5;     // elementwise pair mapping
    float c_state = c0[b_p * HH + hid0 + hh_p];
    float h_last  = 0.f;
    const float* wrow = &sw[r * 516];
    unsigned gen = 0;
    __syncthreads();

    for (int s = 0; s < TT; s++) {
        const float* hsrc = g_hbuf[s & 1];

        // Prefetch x-projection gates for this thread's (b, hh)
        size_t gbase = ((size_t)s * BB + b_p) * NG + hid0 + hh_p;
        float gx0 = __ldg(&g_gates[gbase]);
        float gx1 = __ldg(&g_gates[gbase + 512]);
        float gx2 = __ldg(&g_gates[gbase + 1024]);
        float gx3 = __ldg(&g_gates[gbase + 1536]);

        // Recurrent GEMM slice: acc[u] = dot(h[bg*4+u, :], W_hh_row r)
        float acc0 = 0.f, acc1 = 0.f, acc2 = 0.f, acc3 = 0.f;
        const float* hb = hsrc + bg * 4 * HH;
#pragma unroll 4
        for (int k = 0; k < HH; k += 4) {
            float4 w  = *(const float4*)&wrow[k];
            float4 h0 = __ldcg((const float4*)(hb + k));
            float4 h1 = __ldcg((const float4*)(hb + HH + k));
            float4 h2 = __ldcg((const float4*)(hb + 2 * HH + k));
            float4 h3 = __ldcg((const float4*)(hb + 3 * HH + k));
            acc0 = fmaf(w.x, h0.x, fmaf(w.y, h0.y, fmaf(w.z, h0.z, fmaf(w.w, h0.w, acc0))));
            acc1 = fmaf(w.x, h1.x, fmaf(w.y, h1.y, fmaf(w.z, h1.z, fmaf(w.w, h1.w, acc1))));
            acc2 = fmaf(w.x, h2.x, fmaf(w.y, h2.y, fmaf(w.z, h2.z, fmaf(w.w, h2.w, acc2))));
            acc3 = fmaf(w.x, h3.x, fmaf(w.y, h3.y, fmaf(w.z, h3.z, fmaf(w.w, h3.w, acc3))));
        }
        sg[r * 33 + bg * 4 + 0] = acc0;
        sg[r * 33 + bg * 4 + 1] = acc1;
        sg[r * 33 + bg * 4 + 2] = acc2;
        sg[r * 33 + bg * 4 + 3] = acc3;
        __syncthreads();

        // Elementwise LSTM cell for (b_p, hid0 + hh_p)
        float gi = gx0 + sg[(0 + hh_p)  * 33 + b_p];
        float gf = gx1 + sg[(4 + hh_p)  * 33 + b_p];
        float gg = gx2 + sg[(8 + hh_p)  * 33 + b_p];
        float go = gx3 + sg[(12 + hh_p) * 33 + b_p];
        gi = 1.f / (1.f + __expf(-gi));
        gf = 1.f / (1.f + __expf(-gf));
        gg = tanhf(gg);
        go = 1.f / (1.f + __expf(-go));
        c_state = fmaf(gf, c_state, gi * gg);
        float hn = go * tanhf(c_state);
        h_last = hn;

        g_hbuf[(s + 1) & 1][b_p * HH + hid0 + hh_p] = hn;
        out[((size_t)s * BB + b_p) * HH + hid0 + hh_p] = hn;

        // Grid barrier (all 128 CTAs co-resident: 128 thr, ~35 KB SMEM)
        __threadfence();
        __syncthreads();
        if (tid == 0) {
            unsigned a = atomicAdd(&g_bar_count, 1u);
            if (a == gridDim.x - 1u) {
                g_bar_count = 0u;
                __threadfence();
                atomicExch(&g_bar_gen, gen + 1u);
            } else {
                while (*(volatile unsigned int*)&g_bar_gen < gen + 1u) { }
                __threadfence();
            }
        }
        gen++;
        __syncthreads();
    }

    // Finals: h_f then c_f appended after outputs
    out[(size_t)TT * BB * HH + b_p * HH + hid0 + hh_p] = h_last;
    out[(size_t)TT * BB * HH + BB * HH + b_p * HH + hid0 + hh_p] = c_state;
}

// ---------------------------------------------------------------------------
extern "C" void kernel_launch(void* const* d_in, const int* in_sizes, int n_in,
                              void* d_out, int out_size) {
    const float* X   = (const float*)d_in[0];
    const float* h0  = (const float*)d_in[1];
    const float* c0  = (const float*)d_in[2];
    const float* Wih = (const float*)d_in[3];
    const float* Whh = (const float*)d_in[4];
    const float* bih = (const float*)d_in[5];
    const float* bhh = (const float*)d_in[6];
    float* out = (float*)d_out;

    init_kernel<<<64, 256>>>(h0);
    gemm_x_kernel<<<dim3(256, 32), 256>>>(X, Wih, bih, bhh);
    lstm_rec_kernel<<<128, 128>>>(Whh, c0, out);
}

// round 2
// speedup vs baseline: 2.3988x; 2.3988x over previous
#include <cuda_runtime.h>
#include <math.h>

#define TT 1024
#define BB 32
#define II 512
#define HH 512
#define NG 2048   // 4*H

// ---------------------------------------------------------------------------
// Scratch (allocation-free rule: __device__ globals)
// ---------------------------------------------------------------------------
__device__ __align__(16) float g_gates[(size_t)TT * BB * NG]; // 268MB x-projection
__device__ __align__(16) float g_hbuf[2][BB * HH];            // h double buffer
__device__ volatile unsigned int g_arrive[128];               // per-CTA arrival flags
__device__ volatile unsigned int g_release;                   // barrier release epoch

// packed fp32x2 FMA (FFMA2) — PTX-only, 2 FMAs per instruction
__device__ __forceinline__ unsigned long long ffma2(
    unsigned long long a, unsigned long long b, unsigned long long c) {
    unsigned long long d;
    asm("fma.rn.f32x2 %0, %1, %2, %3;" : "=l"(d) : "l"(a), "l"(b), "l"(c));
    return d;
}
union U2 { unsigned long long u; float2 f; };

// ---------------------------------------------------------------------------
// init: h0 -> buffer 0, reset barrier state (graph-replay safe)
// ---------------------------------------------------------------------------
__global__ void init_kernel(const float* __restrict__ h0) {
    int t = blockIdx.x * blockDim.x + threadIdx.x;
    if (t < BB * HH) g_hbuf[0][t] = h0[t];
    if (t < 128) g_arrive[t] = 0u;
    if (t == 0) g_release = 0u;
}

// ---------------------------------------------------------------------------
// gates_x[L=32768][2048] = X[L][512] @ W_ih[2048][512]^T + (b_ih + b_hh)
// ---------------------------------------------------------------------------
__global__ __launch_bounds__(256) void gemm_x_kernel(
    const float* __restrict__ X, const float* __restrict__ W,
    const float* __restrict__ bih, const float* __restrict__ bhh)
{
    __shared__ float As[32][132];
    __shared__ float Bs[32][68];
    const int tid = threadIdx.x;
    const int tx = tid & 15, ty = tid >> 4;
    const int m0 = blockIdx.x * 128, n0 = blockIdx.y * 64;

    float acc[8][4];
#pragma unroll
    for (int i = 0; i < 8; i++)
#pragma unroll
        for (int j = 0; j < 4; j++) acc[i][j] = 0.f;

    for (int k0 = 0; k0 < II; k0 += 32) {
#pragma unroll
        for (int i = 0; i < 4; i++) {
            int q = tid + i * 256;
            int r = q >> 3, c4 = (q & 7) * 4;
            float4 v = *(const float4*)&X[(size_t)(m0 + r) * II + k0 + c4];
            As[c4 + 0][r] = v.x; As[c4 + 1][r] = v.y;
            As[c4 + 2][r] = v.z; As[c4 + 3][r] = v.w;
        }
#pragma unroll
        for (int i = 0; i < 2; i++) {
            int q = tid + i * 256;
            int r = q >> 3, c4 = (q & 7) * 4;
            float4 v = *(const float4*)&W[(size_t)(n0 + r) * II + k0 + c4];
            Bs[c4 + 0][r] = v.x; Bs[c4 + 1][r] = v.y;
            Bs[c4 + 2][r] = v.z; Bs[c4 + 3][r] = v.w;
        }
        __syncthreads();
#pragma unroll
        for (int k = 0; k < 32; k++) {
            float a[8], bf[4];
            *(float4*)&a[0] = *(const float4*)&As[k][ty * 8];
            *(float4*)&a[4] = *(const float4*)&As[k][ty * 8 + 4];
            *(float4*)&bf[0] = *(const float4*)&Bs[k][tx * 4];
#pragma unroll
            for (int i = 0; i < 8; i++)
#pragma unroll
                for (int j = 0; j < 4; j++)
                    acc[i][j] = fmaf(a[i], bf[j], acc[i][j]);
        }
        __syncthreads();
    }

    const int gn = n0 + tx * 4;
    const float b0 = bih[gn + 0] + bhh[gn + 0];
    const float b1 = bih[gn + 1] + bhh[gn + 1];
    const float b2 = bih[gn + 2] + bhh[gn + 2];
    const float b3 = bih[gn + 3] + bhh[gn + 3];
#pragma unroll
    for (int i = 0; i < 8; i++) {
        float4 v = make_float4(acc[i][0] + b0, acc[i][1] + b1,
                               acc[i][2] + b2, acc[i][3] + b3);
        *(float4*)&g_gates[(size_t)(m0 + ty * 8 + i) * NG + gn] = v;
    }
}

// ---------------------------------------------------------------------------
// Persistent recurrence: 128 CTAs x 256 threads.
// CTA owns 4 hidden units -> 16 gate rows (W in SMEM once).
// Per step: stage h (64KB) into SMEM coalesced, GEMM from SMEM with FFMA2,
// K-split-4 reduce, elementwise, flag-based grid barrier (no atomics).
// ---------------------------------------------------------------------------
#define SW_OFF 0
#define SH_OFF 8256                    // 16*516
#define SP_OFF (SH_OFF + 32*516)       // 24768
#define SG_OFF (SP_OFF + 4*16*33)      // 26880
#define SGX_OFF (SG_OFF + 16*33)       // 27408
#define SM_FLOATS (SGX_OFF + 128*4)    // 27920 floats = 111680 B

__global__ __launch_bounds__(256) void lstm_rec_kernel(
    const float* __restrict__ Whh, const float* __restrict__ c0,
    float* __restrict__ out)
{
    extern __shared__ float sm[];
    float* sw  = sm + SW_OFF;    // [16][516] gate rows
    float* sh  = sm + SH_OFF;    // [32][516] h
    float* sp  = sm + SP_OFF;    // [4][16][33] K-partials
    float* sg  = sm + SG_OFF;    // [16][33] reduced gates
    float* sgx = sm + SGX_OFF;   // [4][32][4] x-projection gates

    const int tid  = threadIdx.x;
    const int bid  = blockIdx.x;
    const int hid0 = bid * 4;

    // compute mapping
    const int bq = tid & 7;          // batch base (batches bq, bq+8, bq+16, bq+24)
    const int rp = (tid >> 3) & 7;   // row pair -> rows rp*2, rp*2+1
    const int kq = tid >> 6;         // k-slice 0..3 (128 k each)
    const int k0 = kq << 7;

    // elementwise mapping (tid < 128)
    const int b_p  = tid & 31;
    const int hh_p = tid >> 5;       // 0..3 for tid<128

    // Stage W rows into SMEM once: rows r = g*4+hh <- Whh[g*512 + hid0+hh]
    for (int q = tid; q < 16 * 128; q += 256) {
        int j = q >> 7; int c4 = (q & 127) * 4;
        int g = j >> 2, hh = j & 3;
        float4 v = *(const float4*)&Whh[(size_t)(g * HH + hid0 + hh) * HH + c4];
        *(float4*)&sw[j * 516 + c4] = v;
    }

    float c_state = (tid < 128) ? c0[b_p * HH + hid0 + hh_p] : 0.f;
    float h_last = 0.f;

    const float* wr0 = sw + (rp * 2 + 0) * 516 + k0;
    const float* wr1 = sw + (rp * 2 + 1) * 516 + k0;
    const float* hp0 = sh + (bq +  0) * 516 + k0;
    const float* hp1 = sh + (bq +  8) * 516 + k0;
    const float* hp2 = sh + (bq + 16) * 516 + k0;
    const float* hp3 = sh + (bq + 24) * 516 + k0;

    __syncthreads();

    for (int s = 0; s < TT; s++) {
        // ---- stage h into SMEM (coalesced, L2-coherent) + gx into SMEM ----
        const float* hsrc = g_hbuf[s & 1];
#pragma unroll
        for (int i = 0; i < 16; i++) {
            int p = (tid + i * 256) * 4;          // 0..16383
            int b = p >> 9, k = p & 511;
            float4 v = __ldcg((const float4*)(hsrc + p));
            *(float4*)&sh[b * 516 + k] = v;
        }
        if (tid < 128) {
            int b = tid & 31, g = tid >> 5;
            float4 gv = __ldg((const float4*)&g_gates[((size_t)s * BB + b) * NG + g * 512 + hid0]);
            *(float4*)&sgx[(g * 32 + b) * 4] = gv;
        }
        __syncthreads();

        // ---- recurrent GEMM slice from SMEM: 2 rows x 4 batches, K=128 ----
        unsigned long long acc[2][4][2];
#pragma unroll
        for (int i = 0; i < 2; i++)
#pragma unroll
            for (int j = 0; j < 4; j++) { acc[i][j][0] = 0ull; acc[i][j][1] = 0ull; }

#pragma unroll 4
        for (int kb = 0; kb < 128; kb += 4) {
            ulonglong2 w0 = *(const ulonglong2*)(wr0 + kb);
            ulonglong2 w1 = *(const ulonglong2*)(wr1 + kb);
            ulonglong2 h0 = *(const ulonglong2*)(hp0 + kb);
            ulonglong2 h1 = *(const ulonglong2*)(hp1 + kb);
            ulonglong2 h2 = *(const ulonglong2*)(hp2 + kb);
            ulonglong2 h3 = *(const ulonglong2*)(hp3 + kb);
            acc[0][0][0] = ffma2(w0.x, h0.x, acc[0][0][0]);
            acc[0][0][1] = ffma2(w0.y, h0.y, acc[0][0][1]);
            acc[0][1][0] = ffma2(w0.x, h1.x, acc[0][1][0]);
            acc[0][1][1] = ffma2(w0.y, h1.y, acc[0][1][1]);
            acc[0][2][0] = ffma2(w0.x, h2.x, acc[0][2][0]);
            acc[0][2][1] = ffma2(w0.y, h2.y, acc[0][2][1]);
            acc[0][3][0] = ffma2(w0.x, h3.x, acc[0][3][0]);
            acc[0][3][1] = ffma2(w0.y, h3.y, acc[0][3][1]);
            acc[1][0][0] = ffma2(w1.x, h0.x, acc[1][0][0]);
            acc[1][0][1] = ffma2(w1.y, h0.y, acc[1][0][1]);
            acc[1][1][0] = ffma2(w1.x, h1.x, acc[1][1][0]);
            acc[1][1][1] = ffma2(w1.y, h1.y, acc[1][1][1]);
            acc[1][2][0] = ffma2(w1.x, h2.x, acc[1][2][0]);
            acc[1][2][1] = ffma2(w1.y, h2.y, acc[1][2][1]);
            acc[1][3][0] = ffma2(w1.x, h3.x, acc[1][3][0]);
            acc[1][3][1] = ffma2(w1.y, h3.y, acc[1][3][1]);
        }
#pragma unroll
        for (int i = 0; i < 2; i++)
#pragma unroll
            for (int j = 0; j < 4; j++) {
                U2 a0, a1; a0.u = acc[i][j][0]; a1.u = acc[i][j][1];
                float p = (a0.f.x + a0.f.y) + (a1.f.x + a1.f.y);
                sp[(kq * 16 + rp * 2 + i) * 33 + (bq + 8 * j)] = p;
            }
        __syncthreads();

        // ---- K-reduction: 512 outputs, 2 per thread ----
        {
            int o = tid;            // r = o>>5, b = o&31
            int r = o >> 5, b = o & 31;
            sg[r * 33 + b] = sp[r * 33 + b] + sp[(16 + r) * 33 + b]
                           + sp[(32 + r) * 33 + b] + sp[(48 + r) * 33 + b];
            o = tid + 256; r = o >> 5; b = o & 31;
            sg[r * 33 + b] = sp[r * 33 + b] + sp[(16 + r) * 33 + b]
                           + sp[(32 + r) * 33 + b] + sp[(48 + r) * 33 + b];
        }
        __syncthreads();

        // ---- elementwise LSTM cell (tid < 128) ----
        if (tid < 128) {
            float gi = sgx[(0 * 32 + b_p) * 4 + hh_p] + sg[(0  + hh_p) * 33 + b_p];
            float gf = sgx[(1 * 32 + b_p) * 4 + hh_p] + sg[(4  + hh_p) * 33 + b_p];
            float gg = sgx[(2 * 32 + b_p) * 4 + hh_p] + sg[(8  + hh_p) * 33 + b_p];
            float go = sgx[(3 * 32 + b_p) * 4 + hh_p] + sg[(12 + hh_p) * 33 + b_p];
            gi = 1.f / (1.f + __expf(-gi));
            gf = 1.f / (1.f + __expf(-gf));
            gg = tanhf(gg);
            go = 1.f / (1.f + __expf(-go));
            c_state = fmaf(gf, c_state, gi * gg);
            float hn = go * tanhf(c_state);
            h_last = hn;
            g_hbuf[(s + 1) & 1][b_p * HH + hid0 + hh_p] = hn;
            out[((size_t)s * BB + b_p) * HH + hid0 + hh_p] = hn;
        }

        // ---- flag-based grid barrier (no atomics) ----
        __threadfence();
        __syncthreads();
        unsigned epoch = (unsigned)(s + 1);
        if (tid == 0) g_arrive[bid] = epoch;        // volatile store
        if (bid == 0) {
            if (tid < 128) {
                while (g_arrive[tid] < epoch) { }
            }
            __syncthreads();
            if (tid == 0) { __threadfence(); g_release = epoch; }
        }
        if (tid == 0) {
            while (g_release < epoch) { }
        }
        __syncthreads();
    }

    if (tid < 128) {
        out[(size_t)TT * BB * HH + b_p * HH + hid0 + hh_p] = h_last;
        out[(size_t)TT * BB * HH + BB * HH + b_p * HH + hid0 + hh_p] = c_state;
    }
}

// ---------------------------------------------------------------------------
extern "C" void kernel_launch(void* const* d_in, const int* in_sizes, int n_in,
                              void* d_out, int out_size) {
    const float* X   = (const float*)d_in[0];
    const float* h0  = (const float*)d_in[1];
    const float* c0  = (const float*)d_in[2];
    const float* Wih = (const float*)d_in[3];
    const float* Whh = (const float*)d_in[4];
    const float* bih = (const float*)d_in[5];
    const float* bhh = (const float*)d_in[6];
    float* out = (float*)d_out;

    cudaFuncSetAttribute(lstm_rec_kernel,
                         cudaFuncAttributeMaxDynamicSharedMemorySize,
                         SM_FLOATS * sizeof(float));

    init_kernel<<<64, 256>>>(h0);
    gemm_x_kernel<<<dim3(256, 32), 256>>>(X, Wih, bih, bhh);
    lstm_rec_kernel<<<128, 256, SM_FLOATS * sizeof(float)>>>(Whh, c0, out);
}